// round 6
// baseline (speedup 1.0000x reference)
#include <cuda_runtime.h>
#include <cuda_bf16.h>
#include <math.h>

#define B_  512
#define S_  128
#define F_  128
#define H_  512
#define H2_ 1024
#define G3_ 1536
#define KAUG 416  // 3*129 padded to /32

// ---------------- device scratch ----------------
__device__ float          g_h[B_*H_];
__device__ __nv_bfloat16  g_S[B_*H_];
__device__ __nv_bfloat16  g_a[B_*H2_];
__device__ float          g_k[5][B_*H_];
__device__ __nv_bfloat16  g_w1b[H_*H2_];
__device__ __nv_bfloat16  g_w2b[H2_*H_];
__device__ __nv_bfloat16  g_Bp[G3_*G3_];            // [Whi;Whi;Wlo] (k,n) for gh
__device__ __nv_bfloat16  g_Ap[B_*G3_];             // [hi(h),lo(h),hi(h)]
__device__ float          g_gh[B_*G3_];
__device__ float          g_gi[(size_t)B_*S_*G3_];  // precomputed input gates
__device__ __nv_bfloat16  g_Ax[(size_t)B_*S_*KAUG];
__device__ __nv_bfloat16  g_Bx[KAUG*G3_];
__device__ float          g_sub[S_];
__device__ unsigned       g_barc[8];

__constant__ float c_next[6][6] = {
  {0.2f,0.f,0.f,0.f,0.f,0.f},
  {0.075f,0.225f,0.f,0.f,0.f,0.f},
  {(float)(44.0/45.0),(float)(-56.0/15.0),(float)(32.0/9.0),0.f,0.f,0.f},
  {(float)(19372.0/6561.0),(float)(-25360.0/2187.0),(float)(64448.0/6561.0),(float)(-212.0/729.0),0.f,0.f},
  {(float)(9017.0/3168.0),(float)(-355.0/33.0),(float)(46732.0/5247.0),(float)(49.0/176.0),(float)(-5103.0/18656.0),0.f},
  {(float)(35.0/384.0),0.f,(float)(500.0/1113.0),(float)(125.0/192.0),(float)(-2187.0/6784.0),(float)(11.0/84.0)}
};

// ---------------- prep kernels ----------------
__global__ void k_prep(const float* __restrict__ tp){
  __shared__ float tm[S_];
  int s = threadIdx.x;
  float acc = 0.f;
  for (int b = 0; b < B_; b++) acc += tp[b*S_ + s];
  tm[s] = acc / (512.0f*72.0f);
  __syncthreads();
  float dtm = (s==0) ? 0.f : (tm[s]-tm[s-1]);
  g_sub[s] = (dtm > 1e-4f) ? dtm/8.0f : 0.f;
}

__global__ void k_init(){
  int i = blockIdx.x*blockDim.x + threadIdx.x;
  if (i < B_*H_){ g_h[i]=0.f; g_S[i]=__float2bfloat16(0.f); }
  if (i < B_*G3_) g_Ap[i]=__float2bfloat16(0.f);
  if (i < 8) g_barc[i] = 0u;
}

__global__ void k_w12(const float* __restrict__ w1, const float* __restrict__ w2){
  int i = blockIdx.x*blockDim.x + threadIdx.x;
  if (i < H_*H2_){ g_w1b[i]=__float2bfloat16(w1[i]); g_w2b[i]=__float2bfloat16(w2[i]); }
}

__global__ void k_bgh(const float* __restrict__ whh){
  int i = blockIdx.x*blockDim.x + threadIdx.x;
  if (i >= G3_*G3_) return;
  int n = i % G3_, k = i / G3_;
  int j = (k<H_) ? k : (k<2*H_ ? k-H_ : k-2*H_);
  float wv = whh[n*H_ + j];
  __nv_bfloat16 hi = __float2bfloat16(wv);
  g_Bp[i] = (k < 2*H_) ? hi : __float2bfloat16(wv - __bfloat162float(hi));
}

__global__ void k_bx(const float* __restrict__ wih){
  int i = blockIdx.x*blockDim.x + threadIdx.x;
  if (i >= KAUG*G3_) return;
  int n = i % G3_, k = i / G3_;
  if (k >= 387){ g_Bx[i]=__float2bfloat16(0.f); return; }
  int j = (k<129) ? k : (k<258 ? k-129 : k-258);
  float wv = wih[n*129 + j];
  __nv_bfloat16 hi = __float2bfloat16(wv);
  g_Bx[i] = (k < 258) ? hi : __float2bfloat16(wv - __bfloat162float(hi));
}

__global__ void k_ax(const float* __restrict__ vals, const float* __restrict__ tp){
  size_t i = (size_t)blockIdx.x*blockDim.x + threadIdx.x;
  if (i >= (size_t)B_*S_*KAUG) return;
  int k = (int)(i % KAUG);
  size_t r = i / KAUG;
  int s = (int)(r % S_), b = (int)(r / S_);
  if (k >= 387){ g_Ax[i]=__float2bfloat16(0.f); return; }
  int j = (k<129) ? k : (k<258 ? k-129 : k-258);
  float x = (j < 128) ? vals[r*F_ + j]
                      : ((s==0) ? 0.f : (tp[b*S_+s]-tp[b*S_+s-1]));
  __nv_bfloat16 hi = __float2bfloat16(x);
  g_Ax[i] = (k<129 || k>=258) ? hi : __float2bfloat16(x - __bfloat162float(hi));
}

// ---------------- mma helpers ----------------
__device__ __forceinline__ void mma_bf16(float* c, const unsigned* a, const unsigned* b){
  asm volatile(
    "mma.sync.aligned.m16n8k16.row.col.f32.bf16.bf16.f32 "
    "{%0,%1,%2,%3},{%4,%5,%6,%7},{%8,%9},{%0,%1,%2,%3};\n"
    : "+f"(c[0]), "+f"(c[1]), "+f"(c[2]), "+f"(c[3])
    : "r"(a[0]), "r"(a[1]), "r"(a[2]), "r"(a[3]), "r"(b[0]), "r"(b[1]));
}
__device__ __forceinline__ void ldsm4(unsigned* r, const __nv_bfloat16* p){
  unsigned a = (unsigned)__cvta_generic_to_shared(p);
  asm volatile("ldmatrix.sync.aligned.m8n8.x4.shared.b16 {%0,%1,%2,%3},[%4];\n"
    : "=r"(r[0]),"=r"(r[1]),"=r"(r[2]),"=r"(r[3]) : "r"(a));
}
__device__ __forceinline__ void ldsm4t(unsigned* r, const __nv_bfloat16* p){
  unsigned a = (unsigned)__cvta_generic_to_shared(p);
  asm volatile("ldmatrix.sync.aligned.m8n8.x4.trans.shared.b16 {%0,%1,%2,%3},[%4];\n"
    : "=r"(r[0]),"=r"(r[1]),"=r"(r[2]),"=r"(r[3]) : "r"(a));
}

// group barrier: release(fence+relaxed add) / acquire-poll. 16 CTAs per group,
// grid = 128 CTAs @ 1 CTA/SM => single wave, all co-resident, no deadlock.
__device__ __forceinline__ void gbar(unsigned* c, unsigned &gen){
  gen += 16;
  __syncthreads();
  if (threadIdx.x == 0){
    __threadfence();
    atomicAdd(c, 1u);
    unsigned v;
    do {
      asm volatile("ld.acquire.gpu.global.u32 %0,[%1];" : "=r"(v) : "l"(c) : "memory");
    } while (v < gen);
  }
  __syncthreads();
}

// ---- 64xTN GEMM, B resident in smem (full K), A double-buffered ----
template<int TN>
__device__ __forceinline__ void gemm_resB(
    const __nv_bfloat16* __restrict__ A, int lda, int K,
    const __nv_bfloat16* Ws, int wstr,
    __nv_bfloat16* As, float (&acc)[2][TN/16][4])
{
  const int t = threadIdx.x;
  const int lane = t&31, w = t>>5;
  const int wm = (w>>1)*32, wn = (w&1)*(TN/2);
  uint4 pa[2];
#pragma unroll
  for (int i=0;i<2;i++){
    int cI = t + i*128;
    pa[i] = *(const uint4*)(A + (size_t)(cI>>2)*lda + (cI&3)*8);
  }
  int buf = 0;
  for (int k0=0; k0<K; k0+=32, buf^=1){
    __nv_bfloat16* Ab = As + buf*(64*40);
#pragma unroll
    for (int i=0;i<2;i++){
      int cI = t + i*128;
      *(uint4*)(Ab + (cI>>2)*40 + (cI&3)*8) = pa[i];
    }
    __syncthreads();
    if (k0+32 < K){
#pragma unroll
      for (int i=0;i<2;i++){
        int cI = t + i*128;
        pa[i] = *(const uint4*)(A + (size_t)(cI>>2)*lda + (k0+32) + (cI&3)*8);
      }
    }
    int l8 = lane&7, gq = lane>>3;
#pragma unroll
    for (int kk=0; kk<32; kk+=16){
      unsigned af[2][4];
#pragma unroll
      for (int tm=0;tm<2;tm++)
        ldsm4(af[tm], Ab + (wm+tm*16+(lane&15))*40 + kk + ((lane>>4)<<3));
#pragma unroll
      for (int tn2=0; tn2<TN/32; tn2++){
        unsigned bfr[4];
        ldsm4t(bfr, Ws + (size_t)(k0+kk+l8+(gq&1)*8)*wstr + wn + tn2*16 + ((gq>>1)<<3));
#pragma unroll
        for (int tm=0;tm<2;tm++)
#pragma unroll
          for (int h2=0; h2<2; h2++){
            unsigned bb[2] = { bfr[h2*2], bfr[h2*2+1] };
            mma_bf16(acc[tm][tn2*2+h2], af[tm], bb);
          }
      }
    }
  }
}

// ---- 64x32 GEMM, B streamed from global (for gh), both double-buffered ----
__device__ __forceinline__ void gemm_strB32(
    const __nv_bfloat16* __restrict__ A, int lda, int K,
    const __nv_bfloat16* __restrict__ Bg, int ldb, int n0,
    __nv_bfloat16* As, __nv_bfloat16* Bs, float (&acc)[2][2][4])
{
  const int t = threadIdx.x;
  const int lane = t&31, w = t>>5;
  const int wm = (w>>1)*32, wn = (w&1)*16;
  uint4 pa[2], pb;
#pragma unroll
  for (int i=0;i<2;i++){
    int cI = t + i*128;
    pa[i] = *(const uint4*)(A + (size_t)(cI>>2)*lda + (cI&3)*8);
  }
  pb = *(const uint4*)(Bg + (size_t)(t>>2)*ldb + n0 + (t&3)*8);
  int buf = 0;
  for (int k0=0; k0<K; k0+=32, buf^=1){
    __nv_bfloat16* Ab = As + buf*(64*40);
    __nv_bfloat16* Bb = Bs + buf*(32*40);
#pragma unroll
    for (int i=0;i<2;i++){
      int cI = t + i*128;
      *(uint4*)(Ab + (cI>>2)*40 + (cI&3)*8) = pa[i];
    }
    *(uint4*)(Bb + (t>>2)*40 + (t&3)*8) = pb;
    __syncthreads();
    if (k0+32 < K){
#pragma unroll
      for (int i=0;i<2;i++){
        int cI = t + i*128;
        pa[i] = *(const uint4*)(A + (size_t)(cI>>2)*lda + (k0+32) + (cI&3)*8);
      }
      pb = *(const uint4*)(Bg + (size_t)(k0+32+(t>>2))*ldb + n0 + (t&3)*8);
    }
    int l8 = lane&7, gq = lane>>3;
#pragma unroll
    for (int kk=0; kk<32; kk+=16){
      unsigned af[2][4];
#pragma unroll
      for (int tm=0;tm<2;tm++)
        ldsm4(af[tm], Ab + (wm+tm*16+(lane&15))*40 + kk + ((lane>>4)<<3));
      unsigned bfr[4];
      ldsm4t(bfr, Bb + (kk+l8+(gq&1)*8)*40 + wn + ((gq>>1)<<3));
#pragma unroll
      for (int tm=0;tm<2;tm++)
#pragma unroll
        for (int h2=0; h2<2; h2++){
          unsigned bb[2] = { bfr[h2*2], bfr[h2*2+1] };
          mma_bf16(acc[tm][h2], af[tm], bb);
        }
    }
  }
}

// ---------------- persistent scan kernel: 8 groups x 16 blocks ----------------
__global__ void __launch_bounds__(128,1) k_scan(
  const float* __restrict__ b1, const float* __restrict__ b2,
  const float* __restrict__ bih, const float* __restrict__ bhh,
  const float* __restrict__ gamma, const float* __restrict__ beta,
  float* __restrict__ out)
{
  extern __shared__ __nv_bfloat16 sm[];
  __nv_bfloat16* Ws1 = sm;                 // 512*72
  __nv_bfloat16* Ws2 = Ws1 + 512*72;       // 1024*40
  __nv_bfloat16* As  = Ws2 + 1024*40;      // 2*64*40
  __nv_bfloat16* Bs  = As  + 2*64*40;      // 2*32*40

  const int t = threadIdx.x;
  const int g = blockIdx.x >> 4;
  const int cb = blockIdx.x & 15;
  const int lane = t&31, w = t>>5;
  const int wm = (w>>1)*32;
  const int qr = lane>>2, qc = lane&3;
  unsigned* barc = &g_barc[g];
  unsigned gen = 0;

  // load resident weight slices
  for (int i=t;i<4096;i+=128){
    int r=i>>3, c8=i&7;
    *(uint4*)(Ws1 + r*72 + c8*8) = *(const uint4*)(g_w1b + (size_t)r*H2_ + cb*64 + c8*8);
  }
  for (int i=t;i<4096;i+=128){
    int r=i>>2, c8=i&3;
    *(uint4*)(Ws2 + r*40 + c8*8) = *(const uint4*)(g_w2b + (size_t)r*H_ + cb*32 + c8*8);
  }
  __syncthreads();

  const __nv_bfloat16* Sg = g_S + g*64*H_;
  const __nv_bfloat16* Ag = g_a + g*64*H2_;
  const __nv_bfloat16* Apg = g_Ap + g*64*G3_;

  for (int s=0; s<S_; s++){
    float sub = g_sub[s];
    if (sub != 0.f){
      for (int u=0; u<8; u++){
        for (int st=1; st<=6; st++){
          { // ---- GEMM1: a = tanh(S @ W1 + b1) ----
            float acc[2][4][4];
#pragma unroll
            for (int i=0;i<2;i++)
#pragma unroll
              for (int j=0;j<4;j++)
#pragma unroll
                for (int e=0;e<4;e++) acc[i][j][e]=0.f;
            gemm_resB<64>(Sg, H_, H_, Ws1, 72, As, acc);
            const int wn = (w&1)*32;
#pragma unroll
            for (int tm=0;tm<2;tm++)
#pragma unroll
              for (int tn=0;tn<4;tn++){
                int r0 = g*64 + wm + tm*16 + qr;
                int c0 = cb*64 + wn + tn*8 + qc*2;
#pragma unroll
                for (int e=0;e<4;e++){
                  int rr = r0 + (e>>1)*8, cc = c0 + (e&1);
                  g_a[(size_t)rr*H2_ + cc] = __float2bfloat16(tanhf(acc[tm][tn][e] + b1[cc]));
                }
              }
          }
          gbar(barc, gen);
          { // ---- GEMM2: k = a @ W2 + b2, RK45 stage epilogue ----
            float acc[2][2][4];
#pragma unroll
            for (int i=0;i<2;i++)
#pragma unroll
              for (int j=0;j<2;j++)
#pragma unroll
                for (int e=0;e<4;e++) acc[i][j][e]=0.f;
            gemm_resB<32>(Ag, H2_, H2_, Ws2, 40, As, acc);
            const int wn = (w&1)*16;
            bool last = (st==6) && (u==7);
#pragma unroll
            for (int tm=0;tm<2;tm++)
#pragma unroll
              for (int tn=0;tn<2;tn++){
                int r0 = g*64 + wm + tm*16 + qr;
                int c0 = cb*32 + wn + tn*8 + qc*2;
#pragma unroll
                for (int e=0;e<4;e++){
                  int rr = r0 + (e>>1)*8, cc = c0 + (e&1);
                  int idx = rr*H_ + cc;
                  float kv = acc[tm][tn][e] + b2[cc];
                  if (st < 6) g_k[st-1][idx] = kv;
                  float sumv = c_next[st-1][st-1]*kv;
#pragma unroll
                  for (int j=0;j<5;j++)
                    if (j < st-1) sumv += c_next[st-1][j]*g_k[j][idx];
                  float sv = g_h[idx] + sub*sumv;
                  if (st == 6){
                    g_h[idx] = sv;
                    if (last){
                      __nv_bfloat16 hi = __float2bfloat16(sv);
                      __nv_bfloat16 lo = __float2bfloat16(sv - __bfloat162float(hi));
                      g_Ap[(size_t)rr*G3_ + cc]        = hi;
                      g_Ap[(size_t)rr*G3_ + H_ + cc]   = lo;
                      g_Ap[(size_t)rr*G3_ + 2*H_ + cc] = hi;
                    }
                  }
                  g_S[idx] = __float2bfloat16(sv);
                }
              }
          }
          gbar(barc, gen);
        }
      }
    }
    // ---- gh GEMM: 3 tiles of 64x32, K=1536 ----
    for (int it=0; it<3; it++){
      float acc[2][2][4];
#pragma unroll
      for (int i=0;i<2;i++)
#pragma unroll
        for (int j=0;j<2;j++)
#pragma unroll
          for (int e=0;e<4;e++) acc[i][j][e]=0.f;
      int n0 = cb*96 + it*32;
      gemm_strB32(Apg, G3_, G3_, g_Bp, G3_, n0, As, Bs, acc);
      const int wn = (w&1)*16;
#pragma unroll
      for (int tm=0;tm<2;tm++)
#pragma unroll
        for (int tn=0;tn<2;tn++){
          int r0 = g*64 + wm + tm*16 + qr;
          int c0 = n0 + wn + tn*8 + qc*2;
#pragma unroll
          for (int e=0;e<4;e++){
            int rr = r0 + (e>>1)*8, cc = c0 + (e&1);
            g_gh[(size_t)rr*G3_ + cc] = acc[tm][tn][e];
          }
        }
    }
    gbar(barc, gen);
    { // ---- GRU + LayerNorm: warp w owns row g*64 + cb*4 + w ----
      int b = g*64 + cb*4 + w;
      const float* gi = g_gi + ((size_t)b*S_ + s)*G3_;
      const float* gh = g_gh + (size_t)b*G3_;
      float v[16]; float lsum = 0.f;
#pragma unroll
      for (int jj=0;jj<16;jj++){
        int j = lane + jj*32;
        float rg = 1.f/(1.f+expf(-(gi[j]      + bih[j]      + gh[j]      + bhh[j])));
        float zg = 1.f/(1.f+expf(-(gi[j+H_]   + bih[j+H_]   + gh[j+H_]   + bhh[j+H_])));
        float ng = tanhf(gi[j+2*H_] + bih[j+2*H_] + rg*(gh[j+2*H_] + bhh[j+2*H_]));
        float hv = (1.f - zg)*ng + zg*g_h[b*H_+j];
        v[jj] = hv; lsum += hv;
      }
#pragma unroll
      for (int jj=0;jj<16;jj++){
        int j = lane + jj*32; float hv = v[jj];
        g_h[b*H_+j] = hv;
        g_S[b*H_+j] = __float2bfloat16(hv);
        __nv_bfloat16 hi = __float2bfloat16(hv);
        __nv_bfloat16 lo = __float2bfloat16(hv - __bfloat162float(hi));
        g_Ap[(size_t)b*G3_ + j]        = hi;
        g_Ap[(size_t)b*G3_ + H_ + j]   = lo;
        g_Ap[(size_t)b*G3_ + 2*H_ + j] = hi;
      }
#pragma unroll
      for (int o=16;o>0;o>>=1) lsum += __shfl_xor_sync(0xffffffffu, lsum, o);
      float mu = lsum / 512.f;
      float lvar = 0.f;
#pragma unroll
      for (int jj=0;jj<16;jj++){ float d = v[jj]-mu; lvar += d*d; }
#pragma unroll
      for (int o=16;o>0;o>>=1) lvar += __shfl_xor_sync(0xffffffffu, lvar, o);
      float inv = rsqrtf(lvar/512.f + 1e-5f);
      float* op = out + ((size_t)b*S_ + s)*H_;
#pragma unroll
      for (int jj=0;jj<16;jj++){
        int j = lane + jj*32;
        op[j] = (v[jj]-mu)*inv*gamma[j] + beta[j];
      }
    }
    gbar(barc, gen);
  }
}

// ---------------- one-time gi GEMM (64x64 tile, streamed A and B) ----------------
__global__ void __launch_bounds__(128) k_gi(){
  __shared__ __nv_bfloat16 As[64*40];
  __shared__ __nv_bfloat16 Bsl[32*72];
  const int t = threadIdx.x;
  const int m0 = blockIdx.y*64, n0 = blockIdx.x*64;
  const int lane = t&31, w = t>>5;
  const int wm = (w>>1)*32, wn = (w&1)*32;
  const int qr = lane>>2, qc = lane&3;
  float acc[2][4][4];
#pragma unroll
  for (int i=0;i<2;i++)
#pragma unroll
    for (int j=0;j<4;j++)
#pragma unroll
      for (int e=0;e<4;e++) acc[i][j][e]=0.f;
  uint4 pa[2], pb[2];
#pragma unroll
  for (int i=0;i<2;i++){
    int cI = t + i*128;
    pa[i] = *(const uint4*)(g_Ax + (size_t)(m0 + (cI>>2))*KAUG + (cI&3)*8);
    pb[i] = *(const uint4*)(g_Bx + (size_t)(cI>>3)*G3_ + n0 + (cI&7)*8);
  }
  for (int k0=0; k0<KAUG; k0+=32){
#pragma unroll
    for (int i=0;i<2;i++){
      int cI = t + i*128;
      *(uint4*)(As + (cI>>2)*40 + (cI&3)*8) = pa[i];
      *(uint4*)(Bsl + (cI>>3)*72 + (cI&7)*8) = pb[i];
    }
    __syncthreads();
    if (k0+32 < KAUG){
#pragma unroll
      for (int i=0;i<2;i++){
        int cI = t + i*128;
        pa[i] = *(const uint4*)(g_Ax + (size_t)(m0 + (cI>>2))*KAUG + (k0+32) + (cI&3)*8);
        pb[i] = *(const uint4*)(g_Bx + (size_t)(k0+32 + (cI>>3))*G3_ + n0 + (cI&7)*8);
      }
    }
    int l8 = lane&7, gq = lane>>3;
#pragma unroll
    for (int kk=0; kk<32; kk+=16){
      unsigned af[2][4];
#pragma unroll
      for (int tm=0;tm<2;tm++)
        ldsm4(af[tm], As + (wm+tm*16+(lane&15))*40 + kk + ((lane>>4)<<3));
#pragma unroll
      for (int tn2=0; tn2<2; tn2++){
        unsigned bfr[4];
        ldsm4t(bfr, Bsl + (kk+l8+(gq&1)*8)*72 + wn + tn2*16 + ((gq>>1)<<3));
#pragma unroll
        for (int tm=0;tm<2;tm++)
#pragma unroll
          for (int h2=0; h2<2; h2++){
            unsigned bb[2] = { bfr[h2*2], bfr[h2*2+1] };
            mma_bf16(acc[tm][tn2*2+h2], af[tm], bb);
          }
      }
    }
    __syncthreads();
  }
#pragma unroll
  for (int tm=0;tm<2;tm++)
#pragma unroll
    for (int tn=0;tn<4;tn++){
      int r0 = m0 + wm + tm*16 + qr;
      int c0 = n0 + wn + tn*8 + qc*2;
#pragma unroll
      for (int e=0;e<4;e++){
        int rr = r0 + (e>>1)*8, cc = c0 + (e&1);
        g_gi[(size_t)rr*G3_ + cc] = acc[tm][tn][e];
      }
    }
}

// ---------------- host ----------------
extern "C" void kernel_launch(void* const* d_in, const int* in_sizes, int n_in,
                              void* d_out, int out_size){
  const float* tp    = (const float*)d_in[0];
  const float* vals  = (const float*)d_in[1];
  const float* w1    = (const float*)d_in[2];
  const float* b1    = (const float*)d_in[3];
  const float* w2    = (const float*)d_in[4];
  const float* b2    = (const float*)d_in[5];
  const float* wih   = (const float*)d_in[6];
  const float* whh   = (const float*)d_in[7];
  const float* bih   = (const float*)d_in[8];
  const float* bhh   = (const float*)d_in[9];
  const float* gamma = (const float*)d_in[10];
  const float* beta  = (const float*)d_in[11];
  float* out = (float*)d_out;
  (void)in_sizes; (void)n_in; (void)out_size;

  const int SMEM = (512*72 + 1024*40 + 2*64*40 + 2*32*40) * 2; // 171008 B
  cudaFuncSetAttribute(k_scan, cudaFuncAttributeMaxDynamicSharedMemorySize, SMEM);

  k_prep<<<1,128>>>(tp);
  k_init<<<(B_*G3_+255)/256,256>>>();
  k_w12<<<(H_*H2_+255)/256,256>>>(w1,w2);
  k_bgh<<<(G3_*G3_+255)/256,256>>>(whh);
  k_bx<<<(KAUG*G3_+255)/256,256>>>(wih);
  {
    size_t n = (size_t)B_*S_*KAUG;
    k_ax<<<(unsigned)((n+255)/256),256>>>(vals,tp);
  }
  k_gi<<<dim3(G3_/64,(B_*S_)/64),128>>>();
  k_scan<<<128,128,SMEM>>>(b1,b2,bih,bhh,gamma,beta,out);
}

// round 7
// speedup vs baseline: 1.1901x; 1.1901x over previous
#include <cuda_runtime.h>
#include <cuda_bf16.h>
#include <math.h>

#define B_  512
#define S_  128
#define F_  128
#define H_  512
#define H2_ 1024
#define G3_ 1536
#define KAUG 416  // 3*129 padded to /32

// ---------------- device scratch ----------------
__device__ float          g_h[B_*H_];
__device__ __nv_bfloat16  g_S[B_*H_];
__device__ __nv_bfloat16  g_a[B_*H2_];
__device__ __nv_bfloat16  g_w1b[H_*H2_];
__device__ __nv_bfloat16  g_w2b[H2_*H_];
__device__ __nv_bfloat16  g_Bp[G3_*G3_];            // [Whi;Whi;Wlo] (k,n) for gh
__device__ __nv_bfloat16  g_Ap[B_*G3_];             // [hi(h),lo(h),hi(h)]
__device__ float          g_gh[B_*G3_];
__device__ float          g_gi[(size_t)B_*S_*G3_];  // precomputed input gates
__device__ __nv_bfloat16  g_Ax[(size_t)B_*S_*KAUG];
__device__ __nv_bfloat16  g_Bx[KAUG*G3_];
__device__ float          g_sub[S_];
__device__ unsigned       g_barc[8];

__constant__ float c_next[6][6] = {
  {0.2f,0.f,0.f,0.f,0.f,0.f},
  {0.075f,0.225f,0.f,0.f,0.f,0.f},
  {(float)(44.0/45.0),(float)(-56.0/15.0),(float)(32.0/9.0),0.f,0.f,0.f},
  {(float)(19372.0/6561.0),(float)(-25360.0/2187.0),(float)(64448.0/6561.0),(float)(-212.0/729.0),0.f,0.f},
  {(float)(9017.0/3168.0),(float)(-355.0/33.0),(float)(46732.0/5247.0),(float)(49.0/176.0),(float)(-5103.0/18656.0),0.f},
  {(float)(35.0/384.0),0.f,(float)(500.0/1113.0),(float)(125.0/192.0),(float)(-2187.0/6784.0),(float)(11.0/84.0)}
};

// ---------------- fused prep (one kernel: all elementwise init) ----------------
__global__ void k_pre(const float* __restrict__ tp, const float* __restrict__ vals,
                      const float* __restrict__ w1, const float* __restrict__ w2,
                      const float* __restrict__ whh, const float* __restrict__ wih){
  size_t i = (size_t)blockIdx.x*256 + threadIdx.x;
  // ---- Ax: [xhi,xlo,xhi] padded, B*S*KAUG elements (largest task) ----
  if (i < (size_t)B_*S_*KAUG){
    int k = (int)(i % KAUG);
    size_t r = i / KAUG;
    int s = (int)(r % S_), b = (int)(r / S_);
    if (k >= 387){ g_Ax[i]=__float2bfloat16(0.f); }
    else {
      int j = (k<129) ? k : (k<258 ? k-129 : k-258);
      float x = (j < 128) ? vals[r*F_ + j]
                          : ((s==0) ? 0.f : (tp[b*S_+s]-tp[b*S_+s-1]));
      __nv_bfloat16 hi = __float2bfloat16(x);
      g_Ax[i] = (k<129 || k>=258) ? hi : __float2bfloat16(x - __bfloat162float(hi));
    }
  }
  // ---- Bp: split whh ----
  if (i < (size_t)G3_*G3_){
    int n = (int)(i % G3_), k = (int)(i / G3_);
    int j = (k<H_) ? k : (k<2*H_ ? k-H_ : k-2*H_);
    float wv = whh[n*H_ + j];
    __nv_bfloat16 hi = __float2bfloat16(wv);
    g_Bp[i] = (k < 2*H_) ? hi : __float2bfloat16(wv - __bfloat162float(hi));
  }
  // ---- Bx: split wih padded ----
  if (i < (size_t)KAUG*G3_){
    int n = (int)(i % G3_), k = (int)(i / G3_);
    if (k >= 387){ g_Bx[i]=__float2bfloat16(0.f); }
    else {
      int j = (k<129) ? k : (k<258 ? k-129 : k-258);
      float wv = wih[n*129 + j];
      __nv_bfloat16 hi = __float2bfloat16(wv);
      g_Bx[i] = (k < 258) ? hi : __float2bfloat16(wv - __bfloat162float(hi));
    }
  }
  // ---- ODE weights to bf16 ----
  if (i < (size_t)H_*H2_){
    g_w1b[i]=__float2bfloat16(w1[i]); g_w2b[i]=__float2bfloat16(w2[i]);
  }
  // ---- state init ----
  if (i < (size_t)B_*G3_) g_Ap[i]=__float2bfloat16(0.f);
  if (i < (size_t)B_*H_){ g_h[i]=0.f; g_S[i]=__float2bfloat16(0.f); }
  if (i < 8) g_barc[i]=0u;
  // ---- dt prep ----
  if (i < S_){
    int s = (int)i; float a0=0.f, a1=0.f;
    for (int b=0;b<B_;b++){ a0 += tp[b*S_+s]; if (s>0) a1 += tp[b*S_+s-1]; }
    float dtm = (s==0) ? 0.f : (a0-a1)/(512.0f*72.0f);
    g_sub[s] = (dtm > 1e-4f) ? dtm/8.0f : 0.f;
  }
}

// ---------------- mma helpers ----------------
__device__ __forceinline__ void mma_bf16(float* c, const unsigned* a, const unsigned* b){
  asm volatile(
    "mma.sync.aligned.m16n8k16.row.col.f32.bf16.bf16.f32 "
    "{%0,%1,%2,%3},{%4,%5,%6,%7},{%8,%9},{%0,%1,%2,%3};\n"
    : "+f"(c[0]), "+f"(c[1]), "+f"(c[2]), "+f"(c[3])
    : "r"(a[0]), "r"(a[1]), "r"(a[2]), "r"(a[3]), "r"(b[0]), "r"(b[1]));
}
__device__ __forceinline__ void ldsm4(unsigned* r, const __nv_bfloat16* p){
  unsigned a = (unsigned)__cvta_generic_to_shared(p);
  asm volatile("ldmatrix.sync.aligned.m8n8.x4.shared.b16 {%0,%1,%2,%3},[%4];\n"
    : "=r"(r[0]),"=r"(r[1]),"=r"(r[2]),"=r"(r[3]) : "r"(a));
}
__device__ __forceinline__ void ldsm4t(unsigned* r, const __nv_bfloat16* p){
  unsigned a = (unsigned)__cvta_generic_to_shared(p);
  asm volatile("ldmatrix.sync.aligned.m8n8.x4.trans.shared.b16 {%0,%1,%2,%3},[%4];\n"
    : "=r"(r[0]),"=r"(r[1]),"=r"(r[2]),"=r"(r[3]) : "r"(a));
}

// group barrier: release(fence+relaxed add) / acquire-poll. 16 CTAs/group,
// grid=128 @ 1 CTA/SM => single wave, all co-resident, no deadlock.
__device__ __forceinline__ void gbar(unsigned* c, unsigned &gen){
  gen += 16;
  __syncthreads();
  if (threadIdx.x == 0){
    __threadfence();
    atomicAdd(c, 1u);
    unsigned v;
    do {
      asm volatile("ld.acquire.gpu.global.u32 %0,[%1];" : "=r"(v) : "l"(c) : "memory");
    } while (v < gen);
  }
  __syncthreads();
}

// ---- 64xTN GEMM, 256 threads (8 warps: 4m x 2n), B resident in smem ----
template<int TN>
__device__ __forceinline__ void gemm8(
    const __nv_bfloat16* __restrict__ A, int lda, int K,
    const __nv_bfloat16* Ws, int wstr,
    __nv_bfloat16* As, float (&acc)[TN/16][4])
{
  const int t=threadIdx.x, lane=t&31, w=t>>5;
  const int wm=(w>>1)*16, wn=(w&1)*(TN/2);
  uint4 pa = *(const uint4*)(A + (size_t)(t>>2)*lda + (t&3)*8);
  int buf=0;
  for (int k0=0;k0<K;k0+=32,buf^=1){
    __nv_bfloat16* Ab = As + buf*(64*40);
    *(uint4*)(Ab + (t>>2)*40 + (t&3)*8) = pa;
    __syncthreads();
    if (k0+32 < K)
      pa = *(const uint4*)(A + (size_t)(t>>2)*lda + (k0+32) + (t&3)*8);
    int l8=lane&7, gq=lane>>3;
#pragma unroll
    for (int kk=0;kk<32;kk+=16){
      unsigned af[4];
      ldsm4(af, Ab + (wm+(lane&15))*40 + kk + ((lane>>4)<<3));
#pragma unroll
      for (int tn2=0;tn2<TN/32;tn2++){
        unsigned bfr[4];
        ldsm4t(bfr, Ws + (size_t)(kk+l8+(gq&1)*8)*wstr + (k0/32)*0 + wn + tn2*16 + ((gq>>1)<<3) + (size_t)k0*wstr);
#pragma unroll
        for (int h2=0;h2<2;h2++){
          unsigned bb[2]={bfr[h2*2],bfr[h2*2+1]};
          mma_bf16(acc[tn2*2+h2], af, bb);
        }
      }
    }
  }
}

// ---- 64x32 GEMM, 256 threads, B streamed from global (for gh) ----
__device__ __forceinline__ void gemm8_strB(
    const __nv_bfloat16* __restrict__ A, int lda, int K,
    const __nv_bfloat16* __restrict__ Bg, int ldb, int n0,
    __nv_bfloat16* As, __nv_bfloat16* Bs, float (&acc)[2][4])
{
  const int t=threadIdx.x, lane=t&31, w=t>>5;
  const int wm=(w>>1)*16, wn=(w&1)*16;
  uint4 pa = *(const uint4*)(A + (size_t)(t>>2)*lda + (t&3)*8);
  uint4 pb;
  if (t < 128) pb = *(const uint4*)(Bg + (size_t)(t>>2)*ldb + n0 + (t&3)*8);
  int buf=0;
  for (int k0=0;k0<K;k0+=32,buf^=1){
    __nv_bfloat16* Ab = As + buf*(64*40);
    __nv_bfloat16* Bb = Bs + buf*(32*40);
    *(uint4*)(Ab + (t>>2)*40 + (t&3)*8) = pa;
    if (t < 128) *(uint4*)(Bb + (t>>2)*40 + (t&3)*8) = pb;
    __syncthreads();
    if (k0+32 < K){
      pa = *(const uint4*)(A + (size_t)(t>>2)*lda + (k0+32) + (t&3)*8);
      if (t < 128) pb = *(const uint4*)(Bg + (size_t)(k0+32+(t>>2))*ldb + n0 + (t&3)*8);
    }
    int l8=lane&7, gq=lane>>3;
#pragma unroll
    for (int kk=0;kk<32;kk+=16){
      unsigned af[4];
      ldsm4(af, Ab + (wm+(lane&15))*40 + kk + ((lane>>4)<<3));
      unsigned bfr[4];
      ldsm4t(bfr, Bb + (kk+l8+(gq&1)*8)*40 + wn + ((gq>>1)<<3));
#pragma unroll
      for (int h2=0;h2<2;h2++){
        unsigned bb[2]={bfr[h2*2],bfr[h2*2+1]};
        mma_bf16(acc[h2], af, bb);
      }
    }
  }
}

// ---------------- persistent scan kernel: 8 groups x 16 CTAs, 256 thr ----------------
__global__ void __launch_bounds__(256,1) k_scan(
  const float* __restrict__ b1, const float* __restrict__ b2,
  const float* __restrict__ bih, const float* __restrict__ bhh,
  const float* __restrict__ gamma, const float* __restrict__ beta,
  float* __restrict__ out)
{
  extern __shared__ __nv_bfloat16 sm[];
  __nv_bfloat16* Ws1 = sm;                         // 512*72  (73728 B)
  __nv_bfloat16* Ws2 = Ws1 + 512*72;               // 1024*40 (81920 B)
  __nv_bfloat16* As  = Ws2 + 1024*40;              // 2*64*40 (10240 B)
  __nv_bfloat16* Bs  = As  + 2*64*40;              // 2*32*40 (5120 B)
  float* kbuf = (float*)(Bs + 2*32*40);            // 5*2048  (40960 B)
  float* hbuf = kbuf + 5*2048;                     // 2048    (8192 B)  total 220160
  __shared__ float red2[16];

  const int t = threadIdx.x;
  const int g = blockIdx.x >> 4;
  const int cb = blockIdx.x & 15;
  const int lane = t&31, w = t>>5;
  const int wm = (w>>1)*16;
  const int qr = lane>>2, qc = lane&3;
  unsigned* barc = &g_barc[g];
  unsigned gen = 0;

  // resident weight slices: W1 cols cb*64.. (stride 72), W2 cols cb*32.. (stride 40)
  for (int i=t;i<4096;i+=256){
    int r=i>>3, c8=i&7;
    *(uint4*)(Ws1 + r*72 + c8*8) = *(const uint4*)(g_w1b + (size_t)r*H2_ + cb*64 + c8*8);
  }
  for (int i=t;i<4096;i+=256){
    int r=i>>2, c8=i&3;
    *(uint4*)(Ws2 + r*40 + c8*8) = *(const uint4*)(g_w2b + (size_t)r*H_ + cb*32 + c8*8);
  }
  __syncthreads();

  const __nv_bfloat16* Sg  = g_S  + g*64*H_;
  const __nv_bfloat16* Ag  = g_a  + g*64*H2_;
  const __nv_bfloat16* Apg = g_Ap + (size_t)g*64*G3_;

  for (int s=0; s<S_; s++){
    // refresh CTA-private h tile from global (post-GRU)
#pragma unroll
    for (int i2=0;i2<8;i2++){
      int idx = t + i2*256;
      hbuf[idx] = g_h[(size_t)(g*64 + (idx>>5))*H_ + cb*32 + (idx&31)];
    }
    __syncthreads();

    float sub = g_sub[s];
    if (sub != 0.f){
      for (int u=0; u<8; u++){
        for (int st=1; st<=6; st++){
          { // ---- GEMM1: a = tanh(S @ W1 + b1), tile 64x64 ----
            float acc[4][4];
#pragma unroll
            for (int j=0;j<4;j++)
#pragma unroll
              for (int e=0;e<4;e++) acc[j][e]=0.f;
            gemm8<64>(Sg, H_, H_, Ws1, 72, As, acc);
            const int wn = (w&1)*32;
#pragma unroll
            for (int tn=0;tn<4;tn++){
              int ccg = cb*64 + wn + tn*8 + qc*2;
              float bb0 = b1[ccg], bb1 = b1[ccg+1];
#pragma unroll
              for (int rh=0;rh<2;rh++){
                int rrg = g*64 + wm + qr + rh*8;
                __nv_bfloat162 v2;
                v2.x = __float2bfloat16(tanhf(acc[tn][rh*2+0] + bb0));
                v2.y = __float2bfloat16(tanhf(acc[tn][rh*2+1] + bb1));
                *(__nv_bfloat162*)(g_a + (size_t)rrg*H2_ + ccg) = v2;
              }
            }
          }
          gbar(barc, gen);
          { // ---- GEMM2: k = a @ W2 + b2, RK45 epilogue (k/h in smem) ----
            float acc[2][4];
#pragma unroll
            for (int j=0;j<2;j++)
#pragma unroll
              for (int e=0;e<4;e++) acc[j][e]=0.f;
            gemm8<32>(Ag, H2_, H2_, Ws2, 40, As, acc);
            const int wn = (w&1)*16;
            bool last = (st==6) && (u==7);
#pragma unroll
            for (int tn=0;tn<2;tn++){
              int cl0 = wn + tn*8 + qc*2;
              int ccg = cb*32 + cl0;
              float bb0 = b2[ccg], bb1 = b2[ccg+1];
#pragma unroll
              for (int rh=0;rh<2;rh++){
                int rl = wm + qr + rh*8;
                int rrg = g*64 + rl;
                float sv[2];
#pragma unroll
                for (int e2=0;e2<2;e2++){
                  int idx = rl*32 + cl0 + e2;
                  float kv = acc[tn][rh*2+e2] + (e2 ? bb1 : bb0);
                  if (st < 6) kbuf[(st-1)*2048 + idx] = kv;
                  float sum = c_next[st-1][st-1]*kv;
#pragma unroll
                  for (int j=0;j<5;j++)
                    if (j < st-1) sum += c_next[st-1][j]*kbuf[j*2048 + idx];
                  float s2 = hbuf[idx] + sub*sum;
                  if (st == 6) hbuf[idx] = s2;
                  sv[e2] = s2;
                }
                if (last){
                  *(float2*)(g_h + (size_t)rrg*H_ + ccg) = make_float2(sv[0], sv[1]);
                  __nv_bfloat162 hi2, lo2;
                  hi2.x = __float2bfloat16(sv[0]);
                  hi2.y = __float2bfloat16(sv[1]);
                  lo2.x = __float2bfloat16(sv[0] - __bfloat162float(hi2.x));
                  lo2.y = __float2bfloat16(sv[1] - __bfloat162float(hi2.y));
                  *(__nv_bfloat162*)(g_Ap + (size_t)rrg*G3_ + ccg)        = hi2;
                  *(__nv_bfloat162*)(g_Ap + (size_t)rrg*G3_ + H_ + ccg)   = lo2;
                  *(__nv_bfloat162*)(g_Ap + (size_t)rrg*G3_ + 2*H_ + ccg) = hi2;
                } else {
                  __nv_bfloat162 s2v;
                  s2v.x = __float2bfloat16(sv[0]);
                  s2v.y = __float2bfloat16(sv[1]);
                  *(__nv_bfloat162*)(g_S + (size_t)rrg*H_ + ccg) = s2v;
                }
              }
            }
          }
          gbar(barc, gen);
        }
      }
    }
    // ---- gh GEMM: 3 tiles of 64x32, K=1536 ----
    for (int it=0; it<3; it++){
      float acc[2][4];
#pragma unroll
      for (int j=0;j<2;j++)
#pragma unroll
        for (int e=0;e<4;e++) acc[j][e]=0.f;
      int n0 = cb*96 + it*32;
      gemm8_strB(Apg, G3_, G3_, g_Bp, G3_, n0, As, Bs, acc);
      const int wn = (w&1)*16;
#pragma unroll
      for (int tn=0;tn<2;tn++){
        int ccg = n0 + wn + tn*8 + qc*2;
#pragma unroll
        for (int rh=0;rh<2;rh++){
          int rrg = g*64 + wm + qr + rh*8;
          *(float2*)(g_gh + (size_t)rrg*G3_ + ccg) =
              make_float2(acc[tn][rh*2+0], acc[tn][rh*2+1]);
        }
      }
    }
    gbar(barc, gen);
    { // ---- GRU + LayerNorm: warp pair (w>>1) owns row, halves by (w&1) ----
      int b = g*64 + cb*4 + (w>>1);
      int half = w&1;
      const float* gi = g_gi + ((size_t)b*S_ + s)*G3_;
      const float* gh = g_gh + (size_t)b*G3_;
      float v[8]; float lsum = 0.f;
#pragma unroll
      for (int jj=0;jj<8;jj++){
        int j = half*256 + lane + jj*32;
        float rg = 1.f/(1.f+expf(-(gi[j]      + bih[j]      + gh[j]      + bhh[j])));
        float zg = 1.f/(1.f+expf(-(gi[j+H_]   + bih[j+H_]   + gh[j+H_]   + bhh[j+H_])));
        float ng = tanhf(gi[j+2*H_] + bih[j+2*H_] + rg*(gh[j+2*H_] + bhh[j+2*H_]));
        float hv = (1.f - zg)*ng + zg*g_h[(size_t)b*H_+j];
        v[jj] = hv; lsum += hv;
      }
#pragma unroll
      for (int jj=0;jj<8;jj++){
        int j = half*256 + lane + jj*32; float hv = v[jj];
        g_h[(size_t)b*H_+j] = hv;
        g_S[(size_t)b*H_+j] = __float2bfloat16(hv);
        __nv_bfloat16 hi = __float2bfloat16(hv);
        __nv_bfloat16 lo = __float2bfloat16(hv - __bfloat162float(hi));
        g_Ap[(size_t)b*G3_ + j]        = hi;
        g_Ap[(size_t)b*G3_ + H_ + j]   = lo;
        g_Ap[(size_t)b*G3_ + 2*H_ + j] = hi;
      }
#pragma unroll
      for (int o=16;o>0;o>>=1) lsum += __shfl_xor_sync(0xffffffffu, lsum, o);
      if (lane==0) red2[w] = lsum;
      __syncthreads();
      float mu = (red2[w & ~1] + red2[w | 1]) / 512.f;
      float lvar = 0.f;
#pragma unroll
      for (int jj=0;jj<8;jj++){ float d = v[jj]-mu; lvar += d*d; }
#pragma unroll
      for (int o=16;o>0;o>>=1) lvar += __shfl_xor_sync(0xffffffffu, lvar, o);
      if (lane==0) red2[8+w] = lvar;
      __syncthreads();
      float inv = rsqrtf((red2[8+(w & ~1)] + red2[8+(w | 1)])/512.f + 1e-5f);
      float* op = out + ((size_t)b*S_ + s)*H_;
#pragma unroll
      for (int jj=0;jj<8;jj++){
        int j = half*256 + lane + jj*32;
        op[j] = (v[jj]-mu)*inv*gamma[j] + beta[j];
      }
    }
    gbar(barc, gen);
  }
}

// ---------------- one-time gi GEMM (64x64 tile, 128 thr, streamed A/B) ----------------
__global__ void __launch_bounds__(128) k_gi(){
  __shared__ __nv_bfloat16 As[64*40];
  __shared__ __nv_bfloat16 Bsl[32*72];
  const int t = threadIdx.x;
  const int m0 = blockIdx.y*64, n0 = blockIdx.x*64;
  const int lane = t&31, w = t>>5;
  const int wm = (w>>1)*32, wn = (w&1)*32;
  const int qr = lane>>2, qc = lane&3;
  float acc[2][4][4];
#pragma unroll
  for (int i=0;i<2;i++)
#pragma unroll
    for (int j=0;j<4;j++)
#pragma unroll
      for (int e=0;e<4;e++) acc[i][j][e]=0.f;
  uint4 pa[2], pb[2];
#pragma unroll
  for (int i=0;i<2;i++){
    int cI = t + i*128;
    pa[i] = *(const uint4*)(g_Ax + (size_t)(m0 + (cI>>2))*KAUG + (cI&3)*8);
    pb[i] = *(const uint4*)(g_Bx + (size_t)(cI>>3)*G3_ + n0 + (cI&7)*8);
  }
  for (int k0=0; k0<KAUG; k0+=32){
#pragma unroll
    for (int i=0;i<2;i++){
      int cI = t + i*128;
      *(uint4*)(As + (cI>>2)*40 + (cI&3)*8) = pa[i];
      *(uint4*)(Bsl + (cI>>3)*72 + (cI&7)*8) = pb[i];
    }
    __syncthreads();
    if (k0+32 < KAUG){
#pragma unroll
      for (int i=0;i<2;i++){
        int cI = t + i*128;
        pa[i] = *(const uint4*)(g_Ax + (size_t)(m0 + (cI>>2))*KAUG + (k0+32) + (cI&3)*8);
        pb[i] = *(const uint4*)(g_Bx + (size_t)(k0+32 + (cI>>3))*G3_ + n0 + (cI&7)*8);
      }
    }
    int l8 = lane&7, gq = lane>>3;
#pragma unroll
    for (int kk=0; kk<32; kk+=16){
      unsigned af[2][4];
#pragma unroll
      for (int tm=0;tm<2;tm++)
        ldsm4(af[tm], As + (wm+tm*16+(lane&15))*40 + kk + ((lane>>4)<<3));
#pragma unroll
      for (int tn2=0; tn2<2; tn2++){
        unsigned bfr[4];
        ldsm4t(bfr, Bsl + (kk+l8+(gq&1)*8)*72 + wn + tn2*16 + ((gq>>1)<<3));
#pragma unroll
        for (int tm=0;tm<2;tm++)
#pragma unroll
          for (int h2=0; h2<2; h2++){
            unsigned bb[2] = { bfr[h2*2], bfr[h2*2+1] };
            mma_bf16(acc[tm][tn2*2+h2], af[tm], bb);
          }
      }
    }
    __syncthreads();
  }
#pragma unroll
  for (int tm=0;tm<2;tm++)
#pragma unroll
    for (int tn=0;tn<4;tn++){
      int r0 = m0 + wm + tm*16 + qr;
      int c0 = n0 + wn + tn*8 + qc*2;
#pragma unroll
      for (int e=0;e<4;e++){
        int rr = r0 + (e>>1)*8, cc = c0 + (e&1);
        g_gi[(size_t)rr*G3_ + cc] = acc[tm][tn][e];
      }
    }
}

// ---------------- host ----------------
extern "C" void kernel_launch(void* const* d_in, const int* in_sizes, int n_in,
                              void* d_out, int out_size){
  const float* tp    = (const float*)d_in[0];
  const float* vals  = (const float*)d_in[1];
  const float* w1    = (const float*)d_in[2];
  const float* b1    = (const float*)d_in[3];
  const float* w2    = (const float*)d_in[4];
  const float* b2    = (const float*)d_in[5];
  const float* wih   = (const float*)d_in[6];
  const float* whh   = (const float*)d_in[7];
  const float* bih   = (const float*)d_in[8];
  const float* bhh   = (const float*)d_in[9];
  const float* gamma = (const float*)d_in[10];
  const float* beta  = (const float*)d_in[11];
  float* out = (float*)d_out;
  (void)in_sizes; (void)n_in; (void)out_size;

  const int SMEM = 512*72*2 + 1024*40*2 + 2*64*40*2 + 2*32*40*2
                 + 5*2048*4 + 2048*4;  // 220160 B
  cudaFuncSetAttribute(k_scan, cudaFuncAttributeMaxDynamicSharedMemorySize, SMEM);

  {
    size_t n = (size_t)B_*S_*KAUG;
    k_pre<<<(unsigned)((n+255)/256),256>>>(tp, vals, w1, w2, whh, wih);
  }
  k_gi<<<dim3(G3_/64,(B_*S_)/64),128>>>();
  k_scan<<<128,256,SMEM>>>(b1,b2,bih,bhh,gamma,beta,out);
}